// round 15
// baseline (speedup 1.0000x reference)
#include <cuda_runtime.h>

// ChunkedValueCrossAttn: softmax over a single context token == 1.0, so
// y[b,c,h,w] = (Wo @ (Wv @ context[b]))[c] + bo[c] — a constant per (b,c)
// broadcast over HxW. x/Wq/Wk are dead inputs.
//
// out: [2, 64, 1024, 1024] f32 = 536.9 MB write-only -> HBM store-bound.
// In-kernel throughput is ~7.25 TB/s (~91% of spec) — at the write ceiling.
//
// This round: TPB=512 (16 warps/block, 2 blocks/SM at the 32-warp cap) —
// halves per-SM prologue instances and block launch/retire events vs
// TPB=256 at identical theoretical occupancy. Prologue unchanged from the
// best kernel (round 12): barrier-free warp-redundant constant via
// y = bo[c] + (Wo[c,:] @ Wv) . ctx, fully coalesced loads, one 5-shfl
// butterfly. 8192 blocks x 512 thr x 4 f4/thread = 32KB/block.

#define B_       2
#define CQ_      64
#define INNER_   32
#define CTX_     16
#define TPB_     512
#define F4_PER_THREAD_ 4
#define F4_PER_BLOCK_  (TPB_ * F4_PER_THREAD_)   // 2048 float4 = 32KB
// 2^18 f4 per slab / 2048 = 128 blocks per slab

__global__ void __launch_bounds__(TPB_) fused_fill_kernel(
        float4* __restrict__ out,
        const float* __restrict__ context,
        const float* __restrict__ Wv,
        const float* __restrict__ Wo,
        const float* __restrict__ bo) {
    unsigned int slab = blockIdx.x >> 7;       // 128 blocks per slab
    unsigned int b = slab >> 6;                // batch index
    unsigned int c = slab & 63u;               // channel index

    const unsigned FULL = 0xFFFFFFFFu;
    int l = threadIdx.x & 31;

    // ctx quarter for this lane: context[b] is 16 floats = 4 float4.
    float4 ctxq = ((const float4*)context)[b * 4 + (l & 3)];
    float wo_l  = Wo[c * INNER_ + l];          // lane l holds Wo[c,l], coalesced
    float bias  = bo[c];                       // uniform broadcast

    // Wv: 32 rows x 16 floats = 128 float4. Iter t, lane l loads float4
    // idx = 32t+l -> row 8t+(l>>2), quarter l&3. Coalesced 512B per iter.
    const float4* Wv4 = (const float4*)Wv;
    float4 acc4 = make_float4(0.f, 0.f, 0.f, 0.f);
    #pragma unroll
    for (int t = 0; t < 4; ++t) {
        float4 w  = Wv4[t * 32 + l];
        float woc = __shfl_sync(FULL, wo_l, 8 * t + (l >> 2));
        acc4.x += woc * w.x;
        acc4.y += woc * w.y;
        acc4.z += woc * w.z;
        acc4.w += woc * w.w;
    }

    // Per-lane partial covers (rows 8t+(l>>2), quarter l&3) exactly once
    // across the warp -> ONE butterfly finishes the double sum.
    float s = acc4.x * ctxq.x + acc4.y * ctxq.y
            + acc4.z * ctxq.z + acc4.w * ctxq.w;
    #pragma unroll
    for (int off = 16; off > 0; off >>= 1)
        s += __shfl_xor_sync(FULL, s, off);    // full sum in ALL lanes

    float val = s + bias;

    float4 f = make_float4(val, val, val, val);
    unsigned int base = blockIdx.x * (unsigned)F4_PER_BLOCK_ + threadIdx.x;
    #pragma unroll
    for (int k = 0; k < F4_PER_THREAD_; ++k)
        out[base + k * (unsigned)TPB_] = f;
}

extern "C" void kernel_launch(void* const* d_in, const int* in_sizes, int n_in,
                              void* d_out, int out_size) {
    // metadata order: x, context, Wq, Wk, Wv, Wo, bo
    const float* context = (const float*)d_in[1];
    const float* Wv      = (const float*)d_in[4];
    const float* Wo      = (const float*)d_in[5];
    const float* bo      = (const float*)d_in[6];

    // out_size = 134,217,728 floats = 33,554,432 float4 -> 8192 blocks exact
    int n4 = out_size / 4;
    int blocks = n4 / F4_PER_BLOCK_;   // 8192
    fused_fill_kernel<<<blocks, TPB_>>>((float4*)d_out, context, Wv, Wo, bo);
}

// round 16
// speedup vs baseline: 1.0038x; 1.0038x over previous
#include <cuda_runtime.h>

// ChunkedValueCrossAttn — FINAL configuration (best measured total: 75.84us).
//
// Math: softmax over a single context token == 1.0, so
// y[b,c,h,w] = (Wo @ (Wv @ context[b]))[c] + bo[c] — a constant per (b,c)
// broadcast over HxW. x/Wq/Wk are dead inputs; the problem reduces to
// computing 128 scalars and writing 536.9 MB.
//
// Measured across 15 rounds: all high-occupancy shapes plateau at
// kernel ~74us / DRAM ~81% / ~7.25 TB/s in-kernel (~91% of HBM3e spec,
// consistent with the path-independent LTS chip cap). This is the floor.
//
// Config: 32768 blocks x 256 threads x 4 float4/thread (16KB/block, each
// block inside one (b,c) slab). Barrier-free, shared-free prologue: every
// warp redundantly computes its constant via the reassociation
// y = bo[c] + (Wo[c,:] @ Wv) . ctx with fully coalesced loads and a single
// 5-shfl butterfly (lane l owns rows 8t+(l>>2) x ctx-quarter l&3 — a
// perfect partition of the 32x16 double sum).

#define B_       2
#define CQ_      64
#define INNER_   32
#define CTX_     16
#define TPB_     256
#define F4_PER_THREAD_ 4
#define F4_PER_BLOCK_  (TPB_ * F4_PER_THREAD_)   // 1024 float4 = 16KB
// 2^18 f4 per slab / 1024 = 256 blocks per slab

__global__ void __launch_bounds__(TPB_) fused_fill_kernel(
        float4* __restrict__ out,
        const float* __restrict__ context,
        const float* __restrict__ Wv,
        const float* __restrict__ Wo,
        const float* __restrict__ bo) {
    unsigned int slab = blockIdx.x >> 8;       // 256 blocks per slab
    unsigned int b = slab >> 6;                // batch index
    unsigned int c = slab & 63u;               // channel index

    const unsigned FULL = 0xFFFFFFFFu;
    int l = threadIdx.x & 31;

    // ctx quarter for this lane: context[b] is 16 floats = 4 float4.
    float4 ctxq = ((const float4*)context)[b * 4 + (l & 3)];
    float wo_l  = Wo[c * INNER_ + l];          // lane l holds Wo[c,l], coalesced
    float bias  = bo[c];                       // uniform broadcast

    // Wv: 32 rows x 16 floats = 128 float4. Iter t, lane l loads float4
    // idx = 32t+l -> row 8t+(l>>2), quarter l&3. Coalesced 512B per iter.
    const float4* Wv4 = (const float4*)Wv;
    float4 acc4 = make_float4(0.f, 0.f, 0.f, 0.f);
    #pragma unroll
    for (int t = 0; t < 4; ++t) {
        float4 w  = Wv4[t * 32 + l];
        float woc = __shfl_sync(FULL, wo_l, 8 * t + (l >> 2));
        acc4.x += woc * w.x;
        acc4.y += woc * w.y;
        acc4.z += woc * w.z;
        acc4.w += woc * w.w;
    }

    // Per-lane partial covers (rows 8t+(l>>2), quarter l&3) exactly once
    // across the warp -> ONE butterfly finishes the double sum.
    float s = acc4.x * ctxq.x + acc4.y * ctxq.y
            + acc4.z * ctxq.z + acc4.w * ctxq.w;
    #pragma unroll
    for (int off = 16; off > 0; off >>= 1)
        s += __shfl_xor_sync(FULL, s, off);    // full sum in ALL lanes

    float val = s + bias;

    float4 f = make_float4(val, val, val, val);
    unsigned int base = blockIdx.x * (unsigned)F4_PER_BLOCK_ + threadIdx.x;
    #pragma unroll
    for (int k = 0; k < F4_PER_THREAD_; ++k)
        out[base + k * (unsigned)TPB_] = f;
}

extern "C" void kernel_launch(void* const* d_in, const int* in_sizes, int n_in,
                              void* d_out, int out_size) {
    // metadata order: x, context, Wq, Wk, Wv, Wo, bo
    const float* context = (const float*)d_in[1];
    const float* Wv      = (const float*)d_in[4];
    const float* Wo      = (const float*)d_in[5];
    const float* bo      = (const float*)d_in[6];

    // out_size = 134,217,728 floats = 33,554,432 float4 -> 32768 blocks exact
    int n4 = out_size / 4;
    int blocks = n4 / F4_PER_BLOCK_;   // 32768
    fused_fill_kernel<<<blocks, TPB_>>>((float4*)d_out, context, Wv, Wo, bo);
}